// round 16
// baseline (speedup 1.0000x reference)
#include <cuda_runtime.h>
#include <cuda_bf16.h>
#include <math.h>
#include <stdint.h>

// LikelihoodRatioEstimator: N=8192, D=512 fp32 inputs. 12 fp32 scalar outputs.
//
// tcgen05 unavailable (harness builds for sm_103 which rejects it).
// Gram matrix via mma.sync bf16 HMMA: 128x256 block, 64x64 warp tile,
// cp.async 3-stage pipeline (R6 mainloop, correctness-validated via means).
// u stored in fp32 — bf16 storage provably biases threshold counts (R6).
// Streaming cache hints (__stcs/__ldcs) on the 268 MB U stream: value-identical,
// keeps L2 available for the GEMM's reused B tiles.
//
// Math identities (validated R3, rel_err 1.58e-4):
//   logit = -log(1+d2), u = 1/(1+d2);  a = S_neg/M = e^lb
//   repulsion.mean == 1; sigmoid(logit-lb) = u/(u+a); (logit-lb)>0 <=> u>a
//   diagonal (positives) computed exactly in fp32 in k_prep.

#define NN 8192
#define DD 512
#define BM 128
#define BN 256
#define BK 32
#define ROWB 80                       // 64B data + 16B pad per k-slice row
#define GT 256
#define GRID_M (NN / BM)              // 64
#define GRID_N (NN / BN)              // 32
#define NBLK (GRID_M * GRID_N)        // 2048
#define A_SZ (BM * ROWB)              // 10240
#define B_SZ (BN * ROWB)              // 20480
#define STAGE_SZ (A_SZ + B_SZ)        // 30720
#define NSTAGE 3
#define DYN_SMEM (NSTAGE * STAGE_SZ)  // 92160
#define KT (DD / BK)                  // 16
#define P2_BLOCKS 2048
#define P2_THREADS 256

// ---------------- scratch (__device__ globals; no allocs allowed) ----------
__device__ float          g_U[(size_t)NN * (size_t)NN];   // u fp32, 268 MB
__device__ __nv_bfloat16  g_Cb[(size_t)NN * DD];
__device__ __nv_bfloat16  g_Tb[(size_t)NN * DD];
__device__ float  g_r2c[NN];
__device__ float  g_r2t[NN];
__device__ float  g_Ud[NN];                   // exact diag u
__device__ float  g_Ld[NN];                   // exact diag log(1+d2)
__device__ double g_pS[NBLK];
__device__ double g_pL[NBLK];
__device__ double g_p2S[P2_BLOCKS];
__device__ unsigned int g_p2C[P2_BLOCKS];
__device__ double g_sc[6];                    // S_all, L_all, S_dA, L_dA, a, lb

// ---------------- helpers ---------------
__device__ __forceinline__ uint32_t smem_u32(const void* p) {
    return (uint32_t)__cvta_generic_to_shared(p);
}
__device__ __forceinline__ void cp_async16(uint32_t dst, const void* src) {
    asm volatile("cp.async.cg.shared.global [%0], [%1], 16;"
                 :: "r"(dst), "l"(src) : "memory");
}

// ---------------------------------------------------------------------------
// Kernel 0: row norms, exact diagonal stats, fp32->bf16 conversion.
// ---------------------------------------------------------------------------
__global__ void k_prep(const float* __restrict__ C, const float* __restrict__ T)
{
    const int lane = threadIdx.x & 31;
    const int row  = blockIdx.x * 8 + (threadIdx.x >> 5);

    const float4* cp = (const float4*)(C + (size_t)row * DD);
    const float4* tp = (const float4*)(T + (size_t)row * DD);
    __nv_bfloat162* cb = (__nv_bfloat162*)(g_Cb + (size_t)row * DD);
    __nv_bfloat162* tb = (__nv_bfloat162*)(g_Tb + (size_t)row * DD);

    float sc = 0.f, st = 0.f, sd = 0.f;
#pragma unroll
    for (int it = 0; it < 4; ++it) {
        int i = lane + 32 * it;
        float4 c = cp[i];
        float4 t = tp[i];
        sc += c.x * c.x + c.y * c.y + c.z * c.z + c.w * c.w;
        st += t.x * t.x + t.y * t.y + t.z * t.z + t.w * t.w;
        float dx = c.x - t.x, dy = c.y - t.y, dz = c.z - t.z, dw = c.w - t.w;
        sd += dx * dx + dy * dy + dz * dz + dw * dw;
        cb[i * 2 + 0] = __float22bfloat162_rn(make_float2(c.x, c.y));
        cb[i * 2 + 1] = __float22bfloat162_rn(make_float2(c.z, c.w));
        tb[i * 2 + 0] = __float22bfloat162_rn(make_float2(t.x, t.y));
        tb[i * 2 + 1] = __float22bfloat162_rn(make_float2(t.z, t.w));
    }
#pragma unroll
    for (int o = 16; o > 0; o >>= 1) {
        sc += __shfl_xor_sync(0xffffffffu, sc, o);
        st += __shfl_xor_sync(0xffffffffu, st, o);
        sd += __shfl_xor_sync(0xffffffffu, sd, o);
    }
    if (lane == 0) {
        g_r2c[row] = sc;
        g_r2t[row] = st;
        float v = 1.0f + fmaxf(sd, 0.0f);
        g_Ud[row] = 1.0f / v;
        g_Ld[row] = logf(v);
    }
}

// ---------------------------------------------------------------------------
// Kernel 1: bf16 HMMA GEMM 128x256, warp tile 64x64, cp.async 3-stage.
// Epilogue: u = 1/(1+d2) -> g_U (fp32, streaming float2 stores), sums of u, log.
// ---------------------------------------------------------------------------
__global__ void __launch_bounds__(GT, 1)
k_gemm()
{
    extern __shared__ __align__(16) unsigned char dsm[];
    __shared__ double red[GT];

    const int tid  = threadIdx.x;
    const int lane = tid & 31;
    const int wid  = tid >> 5;
    const int wm   = wid >> 2;           // 0..1
    const int wn   = wid & 3;            // 0..3
    const int rowBase = blockIdx.x * BM;
    const int colBase = blockIdx.y * BN;

    const uint32_t sBase = smem_u32(dsm);

    const __nv_bfloat16* Abase = g_Cb + (size_t)rowBase * DD;
    const __nv_bfloat16* Bbase = g_Tb + (size_t)colBase * DD;

    // loader mapping: A 512 chunks (2/thread), B 1024 chunks (4/thread); 16B each
#define LOAD_STAGE(slot, kc) do {                                               \
    uint32_t stA = sBase + (slot) * STAGE_SZ;                                   \
    uint32_t stB = stA + A_SZ;                                                  \
    const __nv_bfloat16* aS = Abase + (kc) * BK;                                \
    const __nv_bfloat16* bS = Bbase + (kc) * BK;                                \
    _Pragma("unroll")                                                           \
    for (int i = 0; i < 2; i++) {                                               \
        int q = i * GT + tid; int r = q >> 2; int c = q & 3;                    \
        cp_async16(stA + r * ROWB + c * 16, aS + (size_t)r * DD + c * 8);       \
    }                                                                           \
    _Pragma("unroll")                                                           \
    for (int i = 0; i < 4; i++) {                                               \
        int q = i * GT + tid; int r = q >> 2; int c = q & 3;                    \
        cp_async16(stB + r * ROWB + c * 16, bS + (size_t)r * DD + c * 8);       \
    }                                                                           \
    asm volatile("cp.async.commit_group;" ::: "memory");                        \
} while (0)

    // ldmatrix lane addressing (validated R3/R6)
    const int aRow = wm * 64 + (lane & 15);
    const int aCh  = (lane >> 4) * 16;
    const int bRow = wn * 64 + ((lane >> 4) << 3) + (lane & 7);
    const int bCh  = ((lane >> 3) & 1) * 16;

    float acc[4][8][4];
#pragma unroll
    for (int mf = 0; mf < 4; ++mf)
#pragma unroll
        for (int nf = 0; nf < 8; ++nf)
#pragma unroll
            for (int e = 0; e < 4; ++e) acc[mf][nf][e] = 0.f;

    LOAD_STAGE(0, 0);
    LOAD_STAGE(1, 1);

    for (int kt = 0; kt < KT; ++kt) {
        if (kt < KT - 1) asm volatile("cp.async.wait_group 1;" ::: "memory");
        else             asm volatile("cp.async.wait_group 0;" ::: "memory");
        __syncthreads();
        if (kt + 2 < KT) LOAD_STAGE((kt + 2) % NSTAGE, kt + 2);

        const uint32_t stA = sBase + (kt % NSTAGE) * STAGE_SZ;
        const uint32_t stB = stA + A_SZ;
        const uint32_t aAddr0 = stA + aRow * ROWB + aCh;
        const uint32_t bAddr0 = stB + bRow * ROWB + bCh;

#pragma unroll
        for (int ks = 0; ks < 2; ++ks) {
            uint32_t af[4][4];
            uint32_t bf[4][4];   // [pair]{b0(2p),b1(2p),b0(2p+1),b1(2p+1)}
#pragma unroll
            for (int mf = 0; mf < 4; ++mf) {
                uint32_t addr = aAddr0 + mf * (16 * ROWB) + ks * 32;
                asm volatile(
                    "ldmatrix.sync.aligned.m8n8.x4.shared.b16 {%0,%1,%2,%3}, [%4];"
                    : "=r"(af[mf][0]), "=r"(af[mf][1]),
                      "=r"(af[mf][2]), "=r"(af[mf][3]) : "r"(addr));
            }
#pragma unroll
            for (int p = 0; p < 4; ++p) {
                uint32_t addr = bAddr0 + p * (16 * ROWB) + ks * 32;
                asm volatile(
                    "ldmatrix.sync.aligned.m8n8.x4.shared.b16 {%0,%1,%2,%3}, [%4];"
                    : "=r"(bf[p][0]), "=r"(bf[p][1]),
                      "=r"(bf[p][2]), "=r"(bf[p][3]) : "r"(addr));
            }
#pragma unroll
            for (int mf = 0; mf < 4; ++mf)
#pragma unroll
                for (int nf = 0; nf < 8; ++nf) {
                    const uint32_t b0 = bf[nf >> 1][(nf & 1) * 2 + 0];
                    const uint32_t b1 = bf[nf >> 1][(nf & 1) * 2 + 1];
                    asm volatile(
                        "mma.sync.aligned.m16n8k16.row.col.f32.bf16.bf16.f32 "
                        "{%0,%1,%2,%3}, {%4,%5,%6,%7}, {%8,%9}, {%0,%1,%2,%3};"
                        : "+f"(acc[mf][nf][0]), "+f"(acc[mf][nf][1]),
                          "+f"(acc[mf][nf][2]), "+f"(acc[mf][nf][3])
                        : "r"(af[mf][0]), "r"(af[mf][1]),
                          "r"(af[mf][2]), "r"(af[mf][3]),
                          "r"(b0), "r"(b1));
                }
        }
    }

    // ---- epilogue: u = 1/(1+d2) -> fp32 streaming stores; sums of u, log ----
    float sU = 0.f, sL = 0.f;
#pragma unroll
    for (int mf = 0; mf < 4; ++mf) {
        const int r0 = rowBase + wm * 64 + mf * 16 + (lane >> 2);
        const int r1 = r0 + 8;
        const float r2a = g_r2c[r0];
        const float r2b = g_r2c[r1];
#pragma unroll
        for (int nf = 0; nf < 8; ++nf) {
            const int c0 = colBase + wn * 64 + nf * 8 + 2 * (lane & 3);
            const float q0 = g_r2t[c0];
            const float q1 = g_r2t[c0 + 1];

            float v00 = 1.0f + fmaxf(r2a + q0 - 2.0f * acc[mf][nf][0], 0.0f);
            float v01 = 1.0f + fmaxf(r2a + q1 - 2.0f * acc[mf][nf][1], 0.0f);
            float v10 = 1.0f + fmaxf(r2b + q0 - 2.0f * acc[mf][nf][2], 0.0f);
            float v11 = 1.0f + fmaxf(r2b + q1 - 2.0f * acc[mf][nf][3], 0.0f);
            float u00 = __frcp_rn(v00), u01 = __frcp_rn(v01);
            float u10 = __frcp_rn(v10), u11 = __frcp_rn(v11);
            sU += (u00 + u01) + (u10 + u11);
            sL += (__logf(v00) + __logf(v01)) + (__logf(v10) + __logf(v11));

            __stcs((float2*)(g_U + (size_t)r0 * NN + c0), make_float2(u00, u01));
            __stcs((float2*)(g_U + (size_t)r1 * NN + c0), make_float2(u10, u11));
        }
    }

    // deterministic block reductions
    red[tid] = (double)sU;
    __syncthreads();
#pragma unroll
    for (int s = GT / 2; s > 0; s >>= 1) {
        if (tid < s) red[tid] += red[tid + s];
        __syncthreads();
    }
    if (tid == 0) g_pS[blockIdx.y * GRID_M + blockIdx.x] = red[0];
    __syncthreads();

    red[tid] = (double)sL;
    __syncthreads();
#pragma unroll
    for (int s = GT / 2; s > 0; s >>= 1) {
        if (tid < s) red[tid] += red[tid + s];
        __syncthreads();
    }
    if (tid == 0) g_pL[blockIdx.y * GRID_M + blockIdx.x] = red[0];
}

// ---------------------------------------------------------------------------
// Kernel 2: reduce pass-1 partials + APPROX diagonal sums; compute a and lb.
// ---------------------------------------------------------------------------
__global__ void k_reduce1()
{
    __shared__ double sh[256];
    const int tid = threadIdx.x;

    double vS = 0.0, vL = 0.0, vSd = 0.0, vLd = 0.0;
    for (int b = tid; b < NBLK; b += 256) { vS += g_pS[b]; vL += g_pL[b]; }
    for (int i = tid; i < NN; i += 256) {
        float ua = g_U[(size_t)i * NN + i];       // approx diag u
        vSd += (double)ua;
        vLd += (double)(-__logf(ua));
    }

    double vals[4] = {vS, vL, vSd, vLd};
    double outv[4];
#pragma unroll
    for (int q = 0; q < 4; ++q) {
        sh[tid] = vals[q];
        __syncthreads();
        for (int s = 128; s > 0; s >>= 1) {
            if (tid < s) sh[tid] += sh[tid + s];
            __syncthreads();
        }
        outv[q] = sh[0];
        __syncthreads();
    }

    if (tid == 0) {
        const double M = (double)NN * (double)(NN - 1);
        const double S_neg = outv[0] - outv[2];
        g_sc[0] = outv[0];
        g_sc[1] = outv[1];
        g_sc[2] = outv[2];
        g_sc[3] = outv[3];
        g_sc[4] = S_neg / M;
        g_sc[5] = log(S_neg) - log(M);
    }
}

// ---------------------------------------------------------------------------
// Kernel 3: pass 2 over g_U (fp32, streaming loads): sum u/(u+a), count u>a.
// ---------------------------------------------------------------------------
__global__ void __launch_bounds__(P2_THREADS)
k_pass2()
{
    __shared__ double shS[P2_THREADS];
    __shared__ unsigned int shC[P2_THREADS];

    const float a = (float)g_sc[4];
    const size_t stride = (size_t)gridDim.x * blockDim.x;
    size_t idx = (size_t)blockIdx.x * blockDim.x + threadIdx.x;
    const float4* U4 = (const float4*)g_U;
    const size_t n4 = ((size_t)NN * (size_t)NN) / 4;

    float fs = 0.f;
    unsigned int cnt = 0;
    for (size_t i = idx; i < n4; i += stride) {
        float4 u = __ldcs(U4 + i);
        fs += __fdividef(u.x, u.x + a);
        fs += __fdividef(u.y, u.y + a);
        fs += __fdividef(u.z, u.z + a);
        fs += __fdividef(u.w, u.w + a);
        cnt += (unsigned)(u.x > a) + (unsigned)(u.y > a)
             + (unsigned)(u.z > a) + (unsigned)(u.w > a);
    }

    shS[threadIdx.x] = (double)fs;
    shC[threadIdx.x] = cnt;
    __syncthreads();
    for (int s = P2_THREADS / 2; s > 0; s >>= 1) {
        if (threadIdx.x < s) {
            shS[threadIdx.x] += shS[threadIdx.x + s];
            shC[threadIdx.x] += shC[threadIdx.x + s];
        }
        __syncthreads();
    }
    if (threadIdx.x == 0) {
        g_p2S[blockIdx.x] = shS[0];
        g_p2C[blockIdx.x] = shC[0];
    }
}

// ---------------------------------------------------------------------------
// Kernel 4: final reduce + 12 outputs. Off-diag = totals - approx diag;
// positives from exact fp32 diagonal.
// ---------------------------------------------------------------------------
__global__ void k_final(float* __restrict__ out)
{
    __shared__ double sh[256];
    const int tid = threadIdx.x;
    const double a  = g_sc[4];
    const double lb = g_sc[5];
    const float  af = (float)a;

    double vS = 0.0, vC = 0.0;
    double vSdA = 0.0, vCdA = 0.0;
    double vLdE = 0.0, vSdE = 0.0, vCdE = 0.0;
    for (int b = tid; b < P2_BLOCKS; b += 256) {
        vS += g_p2S[b];
        vC += (double)g_p2C[b];
    }
    for (int i = tid; i < NN; i += 256) {
        float ua = g_U[(size_t)i * NN + i];      // approx diag (as pass2 saw it)
        float fsd = __fdividef(ua, ua + af);
        vSdA += (double)fsd;
        if (ua > af) vCdA += 1.0;

        float ue = g_Ud[i];                      // exact diag
        double ude = (double)ue;
        vLdE += (double)g_Ld[i];
        vSdE += ude / (ude + a);
        if ((double)ue > a) vCdE += 1.0;
    }

    double vals[7] = {vS, vC, vSdA, vCdA, vLdE, vSdE, vCdE};
    double o[7];
#pragma unroll
    for (int q = 0; q < 7; ++q) {
        sh[tid] = vals[q];
        __syncthreads();
        for (int s = 128; s > 0; s >>= 1) {
            if (tid < s) sh[tid] += sh[tid + s];
            __syncthreads();
        }
        o[q] = sh[0];
        __syncthreads();
    }

    if (tid == 0) {
        const double S_all = o[0], C_all = o[1];
        const double S_dA = o[2], C_dA = o[3];
        const double L_dE = o[4], S_dE = o[5], C_dE = o[6];
        const double L_all = g_sc[1], L_dA = g_sc[3];
        const double M  = (double)NN * (double)(NN - 1);
        const double Nd = (double)NN;

        const double pos_mean = -L_dE / Nd - lb;
        const double neg_mean = -(L_all - L_dA) / M - lb;
        const double loss     = 1.0 - pos_mean;
        const double sig_pos  = S_dE / Nd;
        const double sig_neg  = (S_all - S_dA) / M;

        const double TP = C_dE / Nd;
        const double FP = (C_all - C_dA) / M;
        const double TN = 1.0 - FP;
        const double FN = 1.0 - TP;
        const double accuracy  = 0.5 * (TP + TN);
        const double precision = TP / (TP + FP);
        const double npv       = TN / (TN + FN);
        const double apv       = 0.5 * (precision + npv);

        out[0]  = (float)loss;
        out[1]  = (float)pos_mean;
        out[2]  = (float)neg_mean;
        out[3]  = (float)sig_pos;
        out[4]  = (float)sig_neg;
        out[5]  = (float)lb;
        out[6]  = (float)accuracy;
        out[7]  = (float)precision;
        out[8]  = (float)npv;
        out[9]  = (float)apv;
        out[10] = (float)TP;
        out[11] = (float)TN;
    }
}

// ---------------------------------------------------------------------------
extern "C" void kernel_launch(void* const* d_in, const int* in_sizes, int n_in,
                              void* d_out, int out_size)
{
    const float* C = (const float*)d_in[0];
    const float* T = (const float*)d_in[1];
    float* out = (float*)d_out;
    (void)in_sizes; (void)n_in; (void)out_size;

    cudaFuncSetAttribute(k_gemm, cudaFuncAttributeMaxDynamicSharedMemorySize, DYN_SMEM);

    k_prep<<<NN / 8, 256>>>(C, T);
    k_gemm<<<dim3(GRID_M, GRID_N), GT, DYN_SMEM>>>();
    k_reduce1<<<1, 256>>>();
    k_pass2<<<P2_BLOCKS, P2_THREADS>>>();
    k_final<<<1, 256>>>(out);
}